// round 16
// baseline (speedup 1.0000x reference)
#include <cuda_runtime.h>
#include <cuda_bf16.h>
#include <cuda_pipeline_primitives.h>
#include <math.h>

// ---------------- problem constants ----------------
#define BATCH 256
#define GENES 4000
#define PATH  128      // P
#define OMICS 3
#define DDIM  (OMICS * GENES)   // 12000
#define HDIM  64
#define ODIM  16
#define GHID  128      // gate hidden
#define CHID  8
#define NCLS  5
#define TOPK  3
#define BNEPS 1e-5f
#define NENT  (BATCH * TOPK)    // 768 expert work items
#define TILE_S 8                // samples per tile
#define MAXTILE 208             // max sum of ceil(cnt_p/8)
#define NSEG  4                 // gene-split factor
#define NWARP 8                 // warps per k4 block
#define CHUNK 16                // genes per cp.async staging chunk

// gate GEMM split-K config
#define KSPLIT 50
#define KC     80     // 50*80 = 4000
#define KB     16
#define GEMM_BLOCKS (BATCH / 64 * KSPLIT)   // 200
#define K1_BLOCKS (GEMM_BLOCKS + PATH)      // 328

// ---------------- device scratch (no allocations allowed) ----------------
__device__ float g_partial[KSPLIT * BATCH * GHID];
__device__ int   g_gene_idx[PATH * GENES];
__device__ int   g_gene_cnt[PATH];
__device__ int   g_entry[NENT];
__device__ float g_wt[NENT];
__device__ int   g_sorted[NENT];
__device__ int   g_tile_p[MAXTILE];
__device__ int   g_tile_s0[MAXTILE];
__device__ int   g_tile_n[MAXTILE];
__device__ int   g_ntiles;
// per-(tile, seg, warp, sample) partial h  — 13.6 MB
__device__ float g_hpart[MAXTILE * NSEG * NWARP * TILE_S * HDIM];
__device__ float g_contrib[NENT * ODIM];

// =============== K1: fused gene-list compaction + gate GEMM ===============
__global__ void __launch_bounds__(256)
k1_fused(const float* __restrict__ gene_mask,
         const float* __restrict__ x,
         const float* __restrict__ w) {
    __shared__ float As[KB][64];
    __shared__ float Bs[KB][GHID];
    __shared__ int sbase;
    __shared__ int wcnt[8];
    __shared__ int woff[8];

    int t = threadIdx.x;

    if (blockIdx.x < GEMM_BLOCKS) {
        int b0 = (blockIdx.x & 3) * 64;
        int k0 = (blockIdx.x >> 2) * KC;
        int rgrp = t >> 5;
        int cgrp = t & 31;

        float acc[8][4];
        #pragma unroll
        for (int i = 0; i < 8; i++)
            #pragma unroll
            for (int j = 0; j < 4; j++) acc[i][j] = 0.0f;

        for (int kb = 0; kb < KC; kb += KB) {
            int kbase = k0 + kb;
            {
                int r = t >> 2;
                int kq = (t & 3) * 4;
                float4 av = *reinterpret_cast<const float4*>(
                    x + (size_t)(b0 + r) * GENES + kbase + kq);
                As[kq + 0][r] = av.x; As[kq + 1][r] = av.y;
                As[kq + 2][r] = av.z; As[kq + 3][r] = av.w;
            }
            #pragma unroll
            for (int i = 0; i < 2; i++) {
                int f = t + i * 256;
                int kk = f >> 5;
                int c = (f & 31) * 4;
                *reinterpret_cast<float4*>(&Bs[kk][c]) =
                    *reinterpret_cast<const float4*>(w + (size_t)(kbase + kk) * GHID + c);
            }
            __syncthreads();
            #pragma unroll
            for (int kk = 0; kk < KB; kk++) {
                float4 b4 = *reinterpret_cast<const float4*>(&Bs[kk][cgrp * 4]);
                float4 a0 = *reinterpret_cast<const float4*>(&As[kk][rgrp * 8]);
                float4 a1 = *reinterpret_cast<const float4*>(&As[kk][rgrp * 8 + 4]);
                float av[8] = {a0.x, a0.y, a0.z, a0.w, a1.x, a1.y, a1.z, a1.w};
                float bv[4] = {b4.x, b4.y, b4.z, b4.w};
                #pragma unroll
                for (int i = 0; i < 8; i++)
                    #pragma unroll
                    for (int j = 0; j < 4; j++)
                        acc[i][j] = fmaf(av[i], bv[j], acc[i][j]);
            }
            __syncthreads();
        }
        float* out = g_partial + (size_t)(blockIdx.x >> 2) * (BATCH * GHID);
        #pragma unroll
        for (int i = 0; i < 8; i++) {
            *reinterpret_cast<float4*>(
                out + (size_t)(b0 + rgrp * 8 + i) * GHID + cgrp * 4) =
                make_float4(acc[i][0], acc[i][1], acc[i][2], acc[i][3]);
        }
    } else {
        // ---- gene-list compaction: mask preloaded to registers, then 16 ballot rounds ----
        int p = blockIdx.x - GEMM_BLOCKS;
        int wid = t >> 5, lane = t & 31;
        float mv[16];
        #pragma unroll
        for (int q = 0; q < 16; q++) {
            int g = q * 256 + t;
            mv[q] = (g < GENES) ? __ldg(gene_mask + (size_t)g * PATH + p) : 0.0f;
        }
        if (t == 0) sbase = 0;
        __syncthreads();
        #pragma unroll
        for (int q = 0; q < 16; q++) {
            int g = q * 256 + t;
            bool pred = (mv[q] != 0.0f);
            unsigned m = __ballot_sync(0xffffffffu, pred);
            if (lane == 0) wcnt[wid] = __popc(m);
            __syncthreads();
            if (t == 0) {
                int s = sbase;
                #pragma unroll
                for (int w8 = 0; w8 < 8; w8++) { woff[w8] = s; s += wcnt[w8]; }
                sbase = s;
            }
            __syncthreads();
            if (pred) {
                int pos = woff[wid] + __popc(m & ((1u << lane) - 1u));
                g_gene_idx[p * GENES + pos] = g;
            }
            __syncthreads();
        }
        if (t == 0) g_gene_cnt[p] = sbase;
    }
}

// =============== K2: fused gate finish (reduce + relu + layer2 + top3) ===============
__global__ void __launch_bounds__(128)
k2_gate_finish(const float* __restrict__ gb1,
               const float* __restrict__ w2,
               const float* __restrict__ b2g,
               float* __restrict__ out_gw) {
    __shared__ float hid[GHID];
    __shared__ float lg[PATH];
    __shared__ float sv[TOPK];
    __shared__ int   si[TOPK];
    int b = blockIdx.x;
    int p = threadIdx.x;

    float s = 0.0f;
    #pragma unroll
    for (int sp = 0; sp < KSPLIT; sp++)
        s += g_partial[(size_t)sp * (BATCH * GHID) + b * GHID + p];
    s += gb1[p];
    hid[p] = fmaxf(s, 0.0f);
    __syncthreads();

    float acc = b2g[p];
    #pragma unroll 8
    for (int k = 0; k < GHID; k++)
        acc = fmaf(hid[k], __ldg(w2 + (size_t)k * PATH + p), acc);
    lg[p] = acc;
    __syncthreads();

    if (p < 32) {
        float v[4];
        #pragma unroll
        for (int q = 0; q < 4; q++) v[q] = lg[p + q * 32];
        #pragma unroll
        for (int k = 0; k < TOPK; k++) {
            float bv = -1e30f; int bi = 0x7fffffff;
            #pragma unroll
            for (int q = 0; q < 4; q++) {
                int idq = p + q * 32;
                if (v[q] > bv || (v[q] == bv && idq < bi)) { bv = v[q]; bi = idq; }
            }
            #pragma unroll
            for (int off = 16; off; off >>= 1) {
                float ov = __shfl_xor_sync(0xffffffffu, bv, off);
                int oi = __shfl_xor_sync(0xffffffffu, bi, off);
                if (ov > bv || (ov == bv && oi < bi)) { bv = ov; bi = oi; }
            }
            if (p == 0) { sv[k] = bv; si[k] = bi; }
            #pragma unroll
            for (int q = 0; q < 4; q++)
                if (p + q * 32 == bi) v[q] = -1e30f;
        }
    }
    __syncthreads();

    float val = 0.0f;
    #pragma unroll
    for (int k = 0; k < TOPK; k++)
        if (si[k] == p) val = 1.0f / (1.0f + expf(-sv[k]));
    out_gw[(size_t)b * PATH + p] = val;
    if (p < TOPK) {
        g_entry[b * TOPK + p] = si[p];
        g_wt[b * TOPK + p] = 1.0f / (1.0f + expf(-sv[p]));
    }
}

// =============== K3: sort — 768 threads, one entry each, atomic slots ===============
// Slot assignment within a pathway is atomic-order nondeterministic, but every
// entry's computed value is independent of its slot -> output bit-identical.
__global__ void __launch_bounds__(NENT)
k3_sort() {
    __shared__ int hist[PATH];
    __shared__ int off[PATH];
    __shared__ int toff[PATH];
    __shared__ int cur[PATH];
    __shared__ int wsumC[4], wsumT[4];
    int tid = threadIdx.x;

    if (tid < PATH) { hist[tid] = 0; cur[tid] = 0; }
    __syncthreads();
    int p_e = g_entry[tid];              // this thread's entry pathway
    atomicAdd(&hist[p_e], 1);
    __syncthreads();

    if (tid < PATH) {
        int p = tid;
        int cnt = hist[p];
        int nt = (cnt + TILE_S - 1) / TILE_S;
        int lane = tid & 31, wrp = tid >> 5;
        int incC = cnt, incT = nt;
        #pragma unroll
        for (int o = 1; o < 32; o <<= 1) {
            int cc = __shfl_up_sync(0xffffffffu, incC, o);
            int tt = __shfl_up_sync(0xffffffffu, incT, o);
            if (lane >= o) { incC += cc; incT += tt; }
        }
        if (lane == 31) { wsumC[wrp] = incC; wsumT[wrp] = incT; }
        __syncwarp();
        off[p] = incC - cnt;     // intra-warp exclusive (temp)
        toff[p] = incT - nt;
    }
    __syncthreads();
    if (tid < PATH) {
        int p = tid;
        int wrp = tid >> 5;
        int baseC = 0, baseT = 0;
        #pragma unroll
        for (int wv = 0; wv < 4; wv++)
            if (wv < wrp) { baseC += wsumC[wv]; baseT += wsumT[wv]; }
        off[p] += baseC;
        toff[p] += baseT;
    }
    __syncthreads();
    // scatter entries
    {
        int pos = off[p_e] + atomicAdd(&cur[p_e], 1);
        g_sorted[pos] = tid;
    }
    // tiles
    if (tid < PATH) {
        int p = tid;
        int cnt = hist[p];
        int nt = (cnt + TILE_S - 1) / TILE_S;
        for (int tt = 0; tt < nt; tt++) {
            int idx = toff[p] + tt;
            g_tile_p[idx] = p;
            g_tile_s0[idx] = off[p] + TILE_S * tt;
            int rem = cnt - TILE_S * tt;
            g_tile_n[idx] = rem < TILE_S ? rem : TILE_S;
        }
        if (tid == 0)
            g_ntiles = wsumT[0] + wsumT[1] + wsumT[2] + wsumT[3];
    }
}

// =============== K4: sparse experts — cp.async gather, per-warp global partials ===============
// block = (tile, gene-segment). No red[] smem, no cross-warp reduce here: each
// warp stores its acc directly to g_hpart (coalesced float2). smem ~29 KB +
// launch_bounds(256,6) -> 6 blocks/SM resident.
__global__ void __launch_bounds__(256, 6)
k4_expert(const float* __restrict__ x_rna,
          const float* __restrict__ x_cnv,
          const float* __restrict__ x_met,
          const float* __restrict__ W1) {
    int blk = blockIdx.x;
    int tnum = blk >> 2;
    int seg  = blk & 3;
    if (tnum >= g_ntiles) return;
    int p  = g_tile_p[tnum];
    int s0 = g_tile_s0[tnum];
    int n  = g_tile_n[tnum];
    if (n <= 0) return;
    int ng = g_gene_cnt[p];
    int qs = (ng * seg) >> 2;
    int qe = (ng * (seg + 1)) >> 2;
    int seglen = qe - qs;

    int tid = threadIdx.x;
    int lane = tid & 31;   // h columns 2*lane, 2*lane+1
    int wrp = tid >> 5;    // warp owns chunk-local genes l = wrp, wrp+8

    __shared__ float wbuf[2][CHUNK][OMICS][HDIM];   // 24 KB
    __shared__ float xbuf[2][CHUNK][32];            // 4 KB (24 used/row)
    __shared__ const float* xbase[OMICS][TILE_S];

    if (tid < OMICS * TILE_S) {
        int omic = tid >> 3, smp = tid & 7;
        int sl = smp < n ? smp : n - 1;
        int bsmp = g_sorted[s0 + sl] / TOPK;
        const float* xp = (omic == 0) ? x_rna : (omic == 1) ? x_cnv : x_met;
        xbase[omic][smp] = xp + (size_t)bsmp * GENES;
    }
    __syncthreads();

    const int* glist = g_gene_idx + p * GENES;
    const float* W1p = W1 + (size_t)p * DDIM * HDIM;

    float acc[2][TILE_S];
    #pragma unroll
    for (int i = 0; i < 2; i++)
        #pragma unroll
        for (int j = 0; j < TILE_S; j++) acc[i][j] = 0.0f;

    auto stage = [&](int k, int buf) {
        int base = qs + k * CHUNK;
        int ck = qe - base; if (ck > CHUNK) ck = CHUNK;
        if (ck <= 0) return;
        int lastg = base + ck - 1;
        int nslots = ck << 6;   // ck * 4 rows * 16 copies
        for (int s = tid; s < nslots; s += 256) {
            int within = s & 15;
            int row = s >> 4;
            int gene = row >> 2;
            int omic = row & 3;
            if (omic < OMICS) {
                int gi = base + gene; if (gi > lastg) gi = lastg;
                int g = __ldg(glist + gi);
                const float* src = W1p + ((size_t)omic * GENES + g) * HDIM + within * 4;
                __pipeline_memcpy_async(&wbuf[buf][gene][omic][within * 4], src, 16);
            }
        }
        int nx = ck << 5;       // ck * 32
        for (int s = tid; s < nx; s += 256) {
            int gene = s >> 5;
            int r = s & 31;
            if (r < OMICS * TILE_S) {
                int omic = r >> 3, smp = r & 7;
                int gi = base + gene; if (gi > lastg) gi = lastg;
                int g = __ldg(glist + gi);
                __pipeline_memcpy_async(&xbuf[buf][gene][r], xbase[omic][smp] + g, 4);
            }
        }
    };

    if (seglen > 0) {
        int nchunks = (seglen + CHUNK - 1) / CHUNK;
        stage(0, 0);
        __pipeline_commit();
        for (int k = 0; k < nchunks; k++) {
            if (k + 1 < nchunks) stage(k + 1, (k + 1) & 1);
            __pipeline_commit();
            __pipeline_wait_prior(1);
            __syncthreads();
            int base = qs + k * CHUNK;
            int ck = qe - base; if (ck > CHUNK) ck = CHUNK;
            int buf = k & 1;
            for (int l = wrp; l < ck; l += 8) {
                #pragma unroll
                for (int omic = 0; omic < OMICS; omic++) {
                    float2 wv = *reinterpret_cast<const float2*>(
                        &wbuf[buf][l][omic][2 * lane]);
                    float4 xa = *reinterpret_cast<const float4*>(
                        &xbuf[buf][l][omic * 8]);
                    float4 xb = *reinterpret_cast<const float4*>(
                        &xbuf[buf][l][omic * 8 + 4]);
                    acc[0][0] = fmaf(wv.x, xa.x, acc[0][0]);
                    acc[0][1] = fmaf(wv.x, xa.y, acc[0][1]);
                    acc[0][2] = fmaf(wv.x, xa.z, acc[0][2]);
                    acc[0][3] = fmaf(wv.x, xa.w, acc[0][3]);
                    acc[0][4] = fmaf(wv.x, xb.x, acc[0][4]);
                    acc[0][5] = fmaf(wv.x, xb.y, acc[0][5]);
                    acc[0][6] = fmaf(wv.x, xb.z, acc[0][6]);
                    acc[0][7] = fmaf(wv.x, xb.w, acc[0][7]);
                    acc[1][0] = fmaf(wv.y, xa.x, acc[1][0]);
                    acc[1][1] = fmaf(wv.y, xa.y, acc[1][1]);
                    acc[1][2] = fmaf(wv.y, xa.z, acc[1][2]);
                    acc[1][3] = fmaf(wv.y, xa.w, acc[1][3]);
                    acc[1][4] = fmaf(wv.y, xb.x, acc[1][4]);
                    acc[1][5] = fmaf(wv.y, xb.y, acc[1][5]);
                    acc[1][6] = fmaf(wv.y, xb.z, acc[1][6]);
                    acc[1][7] = fmaf(wv.y, xb.w, acc[1][7]);
                }
            }
            __syncthreads();
        }
    }

    // store per-warp partials straight to global (coalesced 256B float2 runs)
    {
        float* hp = g_hpart +
            (((size_t)(tnum * NSEG + seg) * NWARP + wrp) * TILE_S) * HDIM;
        #pragma unroll
        for (int sm = 0; sm < TILE_S; sm++) {
            *reinterpret_cast<float2*>(hp + sm * HDIM + 2 * lane) =
                make_float2(acc[0][sm], acc[1][sm]);
        }
    }
}

// =============== K4b: finish — reduce (seg,warp) partials + BN + ReLU + W2 + weight ===============
__global__ void __launch_bounds__(256)
k4b_finish(const float* __restrict__ b1,
           const float* __restrict__ bn_gamma,
           const float* __restrict__ bn_beta,
           const float* __restrict__ bn_mean,
           const float* __restrict__ bn_var,
           const float* __restrict__ W2,
           const float* __restrict__ b2) {
    int tnum = blockIdx.x;
    if (tnum >= g_ntiles) return;
    int p  = g_tile_p[tnum];
    int s0 = g_tile_s0[tnum];
    int n  = g_tile_n[tnum];
    if (n <= 0) return;
    int tid = threadIdx.x;

    __shared__ float hsm[TILE_S][HDIM];
    __shared__ float w2s[HDIM * ODIM];
    __shared__ int   es[TILE_S];

    if (tid < TILE_S) {
        int sl = tid < n ? tid : n - 1;
        es[tid] = g_sorted[s0 + sl];
    }
    const float* W2p = W2 + (size_t)p * HDIM * ODIM;
    for (int j = tid; j < HDIM * ODIM; j += 256) w2s[j] = W2p[j];

    {
        const float* hp = g_hpart + (size_t)tnum * NSEG * NWARP * TILE_S * HDIM;
        #pragma unroll
        for (int rep = 0; rep < 2; rep++) {
            int slot = tid + rep * 256;   // 0..511
            int sm = slot >> 6;
            int hh = slot & 63;
            float a = 0.0f;
            #pragma unroll
            for (int j = 0; j < NSEG * NWARP; j++)   // flat (seg, warp) — fixed order
                a += hp[((size_t)j * TILE_S + sm) * HDIM + hh];
            a += b1[p * HDIM + hh];
            float scale = bn_gamma[p * HDIM + hh] * rsqrtf(bn_var[p * HDIM + hh] + BNEPS);
            a = (a - bn_mean[p * HDIM + hh]) * scale + bn_beta[p * HDIM + hh];
            hsm[sm][hh] = fmaxf(a, 0.0f);
        }
    }
    __syncthreads();

    if (tid < TILE_S * ODIM) {
        int sm = tid >> 4;
        int o = tid & 15;
        if (sm < n) {
            float sum = 0.0f;
            #pragma unroll 8
            for (int h2 = 0; h2 < HDIM; h2++)
                sum = fmaf(hsm[sm][h2], w2s[h2 * ODIM + o], sum);
            sum += b2[p * ODIM + o];
            int e = es[sm];
            g_contrib[(size_t)e * ODIM + o] = sum * g_wt[e];
        }
    }
}

// =============== K5: classifier ===============
__global__ void __launch_bounds__(256)
k5_classifier(const float* __restrict__ cw1,
              const float* __restrict__ cb1,
              const float* __restrict__ cw2,
              const float* __restrict__ cb2,
              float* __restrict__ out_logits) {
    int b = threadIdx.x;
    float feat[ODIM];
    #pragma unroll
    for (int o = 0; o < ODIM; o++)
        feat[o] = g_contrib[((size_t)b * TOPK + 0) * ODIM + o]
                + g_contrib[((size_t)b * TOPK + 1) * ODIM + o]
                + g_contrib[((size_t)b * TOPK + 2) * ODIM + o];
    float h8[CHID];
    #pragma unroll
    for (int c = 0; c < CHID; c++) {
        float s = cb1[c];
        #pragma unroll
        for (int o = 0; o < ODIM; o++)
            s = fmaf(feat[o], __ldg(cw1 + o * CHID + c), s);
        h8[c] = fmaxf(s, 0.0f);
    }
    #pragma unroll
    for (int c5 = 0; c5 < NCLS; c5++) {
        float s = cb2[c5];
        #pragma unroll
        for (int c = 0; c < CHID; c++)
            s = fmaf(h8[c], __ldg(cw2 + c * NCLS + c5), s);
        out_logits[(size_t)b * NCLS + c5] = s;
    }
}

// ---------------- launch ----------------
extern "C" void kernel_launch(void* const* d_in, const int* in_sizes, int n_in,
                              void* d_out, int out_size) {
    const float* x_rna    = (const float*)d_in[0];
    const float* x_cnv    = (const float*)d_in[1];
    const float* x_met    = (const float*)d_in[2];
    const float* gene_mask= (const float*)d_in[3];
    const float* gate_w1  = (const float*)d_in[4];
    const float* gate_b1  = (const float*)d_in[5];
    const float* gate_w2  = (const float*)d_in[6];
    const float* gate_b2  = (const float*)d_in[7];
    const float* W1       = (const float*)d_in[8];
    const float* b1       = (const float*)d_in[9];
    const float* bn_gamma = (const float*)d_in[10];
    const float* bn_beta  = (const float*)d_in[11];
    const float* bn_mean  = (const float*)d_in[12];
    const float* bn_var   = (const float*)d_in[13];
    const float* W2       = (const float*)d_in[14];
    const float* b2       = (const float*)d_in[15];
    const float* cls_w1   = (const float*)d_in[16];
    const float* cls_b1   = (const float*)d_in[17];
    const float* cls_w2   = (const float*)d_in[18];
    const float* cls_b2   = (const float*)d_in[19];
    float* out = (float*)d_out;
    float* out_logits = out;
    float* out_gw = out + BATCH * NCLS;

    k1_fused<<<K1_BLOCKS, 256>>>(gene_mask, x_rna, gate_w1);
    k2_gate_finish<<<BATCH, GHID>>>(gate_b1, gate_w2, gate_b2, out_gw);
    k3_sort<<<1, NENT>>>();
    k4_expert<<<MAXTILE * NSEG, 256>>>(x_rna, x_cnv, x_met, W1);
    k4b_finish<<<MAXTILE, 256>>>(b1, bn_gamma, bn_beta, bn_mean, bn_var, W2, b2);
    k5_classifier<<<1, BATCH>>>(cls_w1, cls_b1, cls_w2, cls_b2, out_logits);
}

// round 17
// speedup vs baseline: 1.1511x; 1.1511x over previous
#include <cuda_runtime.h>
#include <cuda_bf16.h>
#include <cuda_pipeline_primitives.h>
#include <math.h>

// ---------------- problem constants ----------------
#define BATCH 256
#define GENES 4000
#define PATH  128      // P
#define OMICS 3
#define DDIM  (OMICS * GENES)   // 12000
#define HDIM  64
#define ODIM  16
#define GHID  128      // gate hidden
#define CHID  8
#define NCLS  5
#define TOPK  3
#define BNEPS 1e-5f
#define NENT  (BATCH * TOPK)    // 768 expert work items
#define TILE_S 8                // samples per tile
#define MAXTILE 208             // max sum of ceil(cnt_p/8)
#define NSEG  4                 // gene-split factor
#define CHUNK 16                // genes per cp.async staging chunk

// gate GEMM split-K config
#define KSPLIT 50
#define KC     80     // 50*80 = 4000
#define KB     16
#define GEMM_BLOCKS (BATCH / 64 * KSPLIT)   // 200
#define K1_BLOCKS (GEMM_BLOCKS + PATH)      // 328

// ---------------- device scratch (no allocations allowed) ----------------
__device__ float g_partial[KSPLIT * BATCH * GHID];
__device__ int   g_gene_idx[PATH * GENES];
__device__ int   g_gene_cnt[PATH];
__device__ int   g_entry[NENT];
__device__ float g_wt[NENT];
__device__ int   g_sorted[NENT];
__device__ int   g_tile_p[MAXTILE];
__device__ int   g_tile_s0[MAXTILE];
__device__ int   g_tile_n[MAXTILE];
__device__ int   g_ntiles;
__device__ float g_hpart[MAXTILE * NSEG * TILE_S * HDIM];
__device__ float g_contrib[NENT * ODIM];

// =============== K1: fused gene-list compaction + gate GEMM ===============
__global__ void __launch_bounds__(256)
k1_fused(const float* __restrict__ gene_mask,
         const float* __restrict__ x,
         const float* __restrict__ w) {
    __shared__ float As[KB][64];
    __shared__ float Bs[KB][GHID];
    __shared__ int wcnt_s[16 * 8];   // per-(round, warp) counts
    __shared__ int woff_s[16 * 8];   // exclusive bases

    int t = threadIdx.x;

    if (blockIdx.x < GEMM_BLOCKS) {
        int b0 = (blockIdx.x & 3) * 64;
        int k0 = (blockIdx.x >> 2) * KC;
        int rgrp = t >> 5;
        int cgrp = t & 31;

        float acc[8][4];
        #pragma unroll
        for (int i = 0; i < 8; i++)
            #pragma unroll
            for (int j = 0; j < 4; j++) acc[i][j] = 0.0f;

        for (int kb = 0; kb < KC; kb += KB) {
            int kbase = k0 + kb;
            {
                int r = t >> 2;
                int kq = (t & 3) * 4;
                float4 av = *reinterpret_cast<const float4*>(
                    x + (size_t)(b0 + r) * GENES + kbase + kq);
                As[kq + 0][r] = av.x; As[kq + 1][r] = av.y;
                As[kq + 2][r] = av.z; As[kq + 3][r] = av.w;
            }
            #pragma unroll
            for (int i = 0; i < 2; i++) {
                int f = t + i * 256;
                int kk = f >> 5;
                int c = (f & 31) * 4;
                *reinterpret_cast<float4*>(&Bs[kk][c]) =
                    *reinterpret_cast<const float4*>(w + (size_t)(kbase + kk) * GHID + c);
            }
            __syncthreads();
            #pragma unroll
            for (int kk = 0; kk < KB; kk++) {
                float4 b4 = *reinterpret_cast<const float4*>(&Bs[kk][cgrp * 4]);
                float4 a0 = *reinterpret_cast<const float4*>(&As[kk][rgrp * 8]);
                float4 a1 = *reinterpret_cast<const float4*>(&As[kk][rgrp * 8 + 4]);
                float av[8] = {a0.x, a0.y, a0.z, a0.w, a1.x, a1.y, a1.z, a1.w};
                float bv[4] = {b4.x, b4.y, b4.z, b4.w};
                #pragma unroll
                for (int i = 0; i < 8; i++)
                    #pragma unroll
                    for (int j = 0; j < 4; j++)
                        acc[i][j] = fmaf(av[i], bv[j], acc[i][j]);
            }
            __syncthreads();
        }
        float* out = g_partial + (size_t)(blockIdx.x >> 2) * (BATCH * GHID);
        #pragma unroll
        for (int i = 0; i < 8; i++) {
            *reinterpret_cast<float4*>(
                out + (size_t)(b0 + rgrp * 8 + i) * GHID + cgrp * 4) =
                make_float4(acc[i][0], acc[i][1], acc[i][2], acc[i][3]);
        }
    } else {
        // ---- gene-list compaction: all ballots up front, 2 barriers total ----
        int p = blockIdx.x - GEMM_BLOCKS;
        int wid = t >> 5, lane = t & 31;
        unsigned bm[16];
        #pragma unroll
        for (int q = 0; q < 16; q++) {
            int g = q * 256 + t;
            float mvq = (g < GENES) ? __ldg(gene_mask + (size_t)g * PATH + p) : 0.0f;
            bm[q] = __ballot_sync(0xffffffffu, mvq != 0.0f);
            if (lane == 0) wcnt_s[q * 8 + wid] = __popc(bm[q]);
        }
        __syncthreads();
        // exclusive prefix over 128 (round-major, warp-minor) counts
        if (t < 128) {
            int s = 0;
            for (int j = 0; j < t; j++) s += wcnt_s[j];
            woff_s[t] = s;
        }
        __syncthreads();
        // scatter all rounds, barrier-free (positions identical to serial version)
        #pragma unroll
        for (int q = 0; q < 16; q++) {
            if (bm[q] & (1u << lane)) {
                int g = q * 256 + t;
                int pos = woff_s[q * 8 + wid] + __popc(bm[q] & ((1u << lane) - 1u));
                g_gene_idx[p * GENES + pos] = g;
            }
        }
        if (t == 0) {
            // total = last base + last count
            g_gene_cnt[p] = woff_s[127] + wcnt_s[127];
        }
    }
}

// =============== K2: fused gate finish (reduce + relu + layer2 + top3) ===============
__global__ void __launch_bounds__(128)
k2_gate_finish(const float* __restrict__ gb1,
               const float* __restrict__ w2,
               const float* __restrict__ b2g,
               float* __restrict__ out_gw) {
    __shared__ float hid[GHID];
    __shared__ float lg[PATH];
    __shared__ float sv[TOPK];
    __shared__ int   si[TOPK];
    int b = blockIdx.x;
    int p = threadIdx.x;

    float s = 0.0f;
    #pragma unroll
    for (int sp = 0; sp < KSPLIT; sp++)
        s += g_partial[(size_t)sp * (BATCH * GHID) + b * GHID + p];
    s += gb1[p];
    hid[p] = fmaxf(s, 0.0f);
    __syncthreads();

    float acc = b2g[p];
    #pragma unroll 8
    for (int k = 0; k < GHID; k++)
        acc = fmaf(hid[k], __ldg(w2 + (size_t)k * PATH + p), acc);
    lg[p] = acc;
    __syncthreads();

    if (p < 32) {
        float v[4];
        #pragma unroll
        for (int q = 0; q < 4; q++) v[q] = lg[p + q * 32];
        #pragma unroll
        for (int k = 0; k < TOPK; k++) {
            float bv = -1e30f; int bi = 0x7fffffff;
            #pragma unroll
            for (int q = 0; q < 4; q++) {
                int idq = p + q * 32;
                if (v[q] > bv || (v[q] == bv && idq < bi)) { bv = v[q]; bi = idq; }
            }
            #pragma unroll
            for (int off = 16; off; off >>= 1) {
                float ov = __shfl_xor_sync(0xffffffffu, bv, off);
                int oi = __shfl_xor_sync(0xffffffffu, bi, off);
                if (ov > bv || (ov == bv && oi < bi)) { bv = ov; bi = oi; }
            }
            if (p == 0) { sv[k] = bv; si[k] = bi; }
            #pragma unroll
            for (int q = 0; q < 4; q++)
                if (p + q * 32 == bi) v[q] = -1e30f;
        }
    }
    __syncthreads();

    float val = 0.0f;
    #pragma unroll
    for (int k = 0; k < TOPK; k++)
        if (si[k] == p) val = 1.0f / (1.0f + expf(-sv[k]));
    out_gw[(size_t)b * PATH + p] = val;
    if (p < TOPK) {
        g_entry[b * TOPK + p] = si[p];
        g_wt[b * TOPK + p] = 1.0f / (1.0f + expf(-sv[p]));
    }
}

// =============== K3: sort — 768 threads, one entry each, atomic slots ===============
__global__ void __launch_bounds__(NENT)
k3_sort() {
    __shared__ int hist[PATH];
    __shared__ int off[PATH];
    __shared__ int toff[PATH];
    __shared__ int cur[PATH];
    __shared__ int wsumC[4], wsumT[4];
    int tid = threadIdx.x;

    if (tid < PATH) { hist[tid] = 0; cur[tid] = 0; }
    __syncthreads();
    int p_e = g_entry[tid];
    atomicAdd(&hist[p_e], 1);
    __syncthreads();

    if (tid < PATH) {
        int p = tid;
        int cnt = hist[p];
        int nt = (cnt + TILE_S - 1) / TILE_S;
        int lane = tid & 31, wrp = tid >> 5;
        int incC = cnt, incT = nt;
        #pragma unroll
        for (int o = 1; o < 32; o <<= 1) {
            int cc = __shfl_up_sync(0xffffffffu, incC, o);
            int tt = __shfl_up_sync(0xffffffffu, incT, o);
            if (lane >= o) { incC += cc; incT += tt; }
        }
        if (lane == 31) { wsumC[wrp] = incC; wsumT[wrp] = incT; }
        __syncwarp();
        off[p] = incC - cnt;
        toff[p] = incT - nt;
    }
    __syncthreads();
    if (tid < PATH) {
        int p = tid;
        int wrp = tid >> 5;
        int baseC = 0, baseT = 0;
        #pragma unroll
        for (int wv = 0; wv < 4; wv++)
            if (wv < wrp) { baseC += wsumC[wv]; baseT += wsumT[wv]; }
        off[p] += baseC;
        toff[p] += baseT;
    }
    __syncthreads();
    {
        int pos = off[p_e] + atomicAdd(&cur[p_e], 1);
        g_sorted[pos] = tid;
    }
    if (tid < PATH) {
        int p = tid;
        int cnt = hist[p];
        int nt = (cnt + TILE_S - 1) / TILE_S;
        for (int tt = 0; tt < nt; tt++) {
            int idx = toff[p] + tt;
            g_tile_p[idx] = p;
            g_tile_s0[idx] = off[p] + TILE_S * tt;
            int rem = cnt - TILE_S * tt;
            g_tile_n[idx] = rem < TILE_S ? rem : TILE_S;
        }
        if (tid == 0)
            g_ntiles = wsumT[0] + wsumT[1] + wsumT[2] + wsumT[3];
    }
}

// =============== K4: sparse experts — cp.async gather, 8 samples/tile (R15 config) ===============
__global__ void __launch_bounds__(256)
k4_expert(const float* __restrict__ x_rna,
          const float* __restrict__ x_cnv,
          const float* __restrict__ x_met,
          const float* __restrict__ W1) {
    int blk = blockIdx.x;
    int tnum = blk >> 2;
    int seg  = blk & 3;
    if (tnum >= g_ntiles) return;
    int p  = g_tile_p[tnum];
    int s0 = g_tile_s0[tnum];
    int n  = g_tile_n[tnum];
    if (n <= 0) return;
    int ng = g_gene_cnt[p];
    int qs = (ng * seg) >> 2;
    int qe = (ng * (seg + 1)) >> 2;
    int seglen = qe - qs;

    int tid = threadIdx.x;
    int lane = tid & 31;   // h columns 2*lane, 2*lane+1
    int wrp = tid >> 5;    // warp owns chunk-local genes l = wrp, wrp+8

    __shared__ float wbuf[2][CHUNK][OMICS][HDIM];   // 24 KB
    __shared__ float xbuf[2][CHUNK][32];            // 4 KB (24 used/row)
    __shared__ float red[8 * TILE_S * HDIM];        // 16 KB
    __shared__ const float* xbase[OMICS][TILE_S];

    if (tid < OMICS * TILE_S) {
        int omic = tid >> 3, smp = tid & 7;
        int sl = smp < n ? smp : n - 1;
        int bsmp = g_sorted[s0 + sl] / TOPK;
        const float* xp = (omic == 0) ? x_rna : (omic == 1) ? x_cnv : x_met;
        xbase[omic][smp] = xp + (size_t)bsmp * GENES;
    }
    __syncthreads();

    const int* glist = g_gene_idx + p * GENES;
    const float* W1p = W1 + (size_t)p * DDIM * HDIM;

    float acc[2][TILE_S];
    #pragma unroll
    for (int i = 0; i < 2; i++)
        #pragma unroll
        for (int j = 0; j < TILE_S; j++) acc[i][j] = 0.0f;

    auto stage = [&](int k, int buf) {
        int base = qs + k * CHUNK;
        int ck = qe - base; if (ck > CHUNK) ck = CHUNK;
        if (ck <= 0) return;
        int lastg = base + ck - 1;
        int nslots = ck << 6;   // ck * 4 rows * 16 copies
        for (int s = tid; s < nslots; s += 256) {
            int within = s & 15;
            int row = s >> 4;
            int gene = row >> 2;
            int omic = row & 3;
            if (omic < OMICS) {
                int gi = base + gene; if (gi > lastg) gi = lastg;
                int g = __ldg(glist + gi);
                const float* src = W1p + ((size_t)omic * GENES + g) * HDIM + within * 4;
                __pipeline_memcpy_async(&wbuf[buf][gene][omic][within * 4], src, 16);
            }
        }
        int nx = ck << 5;       // ck * 32
        for (int s = tid; s < nx; s += 256) {
            int gene = s >> 5;
            int r = s & 31;
            if (r < OMICS * TILE_S) {
                int omic = r >> 3, smp = r & 7;
                int gi = base + gene; if (gi > lastg) gi = lastg;
                int g = __ldg(glist + gi);
                __pipeline_memcpy_async(&xbuf[buf][gene][r], xbase[omic][smp] + g, 4);
            }
        }
    };

    if (seglen > 0) {
        int nchunks = (seglen + CHUNK - 1) / CHUNK;
        stage(0, 0);
        __pipeline_commit();
        for (int k = 0; k < nchunks; k++) {
            if (k + 1 < nchunks) stage(k + 1, (k + 1) & 1);
            __pipeline_commit();
            __pipeline_wait_prior(1);
            __syncthreads();
            int base = qs + k * CHUNK;
            int ck = qe - base; if (ck > CHUNK) ck = CHUNK;
            int buf = k & 1;
            for (int l = wrp; l < ck; l += 8) {
                #pragma unroll
                for (int omic = 0; omic < OMICS; omic++) {
                    float2 wv = *reinterpret_cast<const float2*>(
                        &wbuf[buf][l][omic][2 * lane]);
                    float4 xa = *reinterpret_cast<const float4*>(
                        &xbuf[buf][l][omic * 8]);
                    float4 xb = *reinterpret_cast<const float4*>(
                        &xbuf[buf][l][omic * 8 + 4]);
                    acc[0][0] = fmaf(wv.x, xa.x, acc[0][0]);
                    acc[0][1] = fmaf(wv.x, xa.y, acc[0][1]);
                    acc[0][2] = fmaf(wv.x, xa.z, acc[0][2]);
                    acc[0][3] = fmaf(wv.x, xa.w, acc[0][3]);
                    acc[0][4] = fmaf(wv.x, xb.x, acc[0][4]);
                    acc[0][5] = fmaf(wv.x, xb.y, acc[0][5]);
                    acc[0][6] = fmaf(wv.x, xb.z, acc[0][6]);
                    acc[0][7] = fmaf(wv.x, xb.w, acc[0][7]);
                    acc[1][0] = fmaf(wv.y, xa.x, acc[1][0]);
                    acc[1][1] = fmaf(wv.y, xa.y, acc[1][1]);
                    acc[1][2] = fmaf(wv.y, xa.z, acc[1][2]);
                    acc[1][3] = fmaf(wv.y, xa.w, acc[1][3]);
                    acc[1][4] = fmaf(wv.y, xb.x, acc[1][4]);
                    acc[1][5] = fmaf(wv.y, xb.y, acc[1][5]);
                    acc[1][6] = fmaf(wv.y, xb.z, acc[1][6]);
                    acc[1][7] = fmaf(wv.y, xb.w, acc[1][7]);
                }
            }
            __syncthreads();
        }
    }

    #pragma unroll
    for (int sm = 0; sm < TILE_S; sm++) {
        *reinterpret_cast<float2*>(
            &red[(wrp * TILE_S + sm) * HDIM + 2 * lane]) =
            make_float2(acc[0][sm], acc[1][sm]);
    }
    __syncthreads();

    {
        float* hp = g_hpart + ((size_t)(tnum * NSEG + seg) * TILE_S) * HDIM;
        #pragma unroll
        for (int rep = 0; rep < 2; rep++) {
            int slot = tid + rep * 256;
            int sm = slot >> 6;
            int hh = slot & 63;
            float a = 0.0f;
            #pragma unroll
            for (int w8 = 0; w8 < 8; w8++)
                a += red[(w8 * TILE_S + sm) * HDIM + hh];
            hp[sm * HDIM + hh] = a;
        }
    }
}

// =============== K4b: finish — reduce segments + BN + ReLU + W2 + weight ===============
__global__ void __launch_bounds__(256)
k4b_finish(const float* __restrict__ b1,
           const float* __restrict__ bn_gamma,
           const float* __restrict__ bn_beta,
           const float* __restrict__ bn_mean,
           const float* __restrict__ bn_var,
           const float* __restrict__ W2,
           const float* __restrict__ b2) {
    int tnum = blockIdx.x;
    if (tnum >= g_ntiles) return;
    int p  = g_tile_p[tnum];
    int s0 = g_tile_s0[tnum];
    int n  = g_tile_n[tnum];
    if (n <= 0) return;
    int tid = threadIdx.x;

    __shared__ float hsm[TILE_S][HDIM];
    __shared__ float w2s[HDIM * ODIM];
    __shared__ int   es[TILE_S];

    if (tid < TILE_S) {
        int sl = tid < n ? tid : n - 1;
        es[tid] = g_sorted[s0 + sl];
    }
    const float* W2p = W2 + (size_t)p * HDIM * ODIM;
    for (int j = tid; j < HDIM * ODIM; j += 256) w2s[j] = W2p[j];

    {
        const float* hp = g_hpart + (size_t)tnum * NSEG * TILE_S * HDIM;
        #pragma unroll
        for (int rep = 0; rep < 2; rep++) {
            int slot = tid + rep * 256;
            int sm = slot >> 6;
            int hh = slot & 63;
            float a = 0.0f;
            #pragma unroll
            for (int q = 0; q < NSEG; q++)
                a += hp[(q * TILE_S + sm) * HDIM + hh];
            a += b1[p * HDIM + hh];
            float scale = bn_gamma[p * HDIM + hh] * rsqrtf(bn_var[p * HDIM + hh] + BNEPS);
            a = (a - bn_mean[p * HDIM + hh]) * scale + bn_beta[p * HDIM + hh];
            hsm[sm][hh] = fmaxf(a, 0.0f);
        }
    }
    __syncthreads();

    if (tid < TILE_S * ODIM) {
        int sm = tid >> 4;
        int o = tid & 15;
        if (sm < n) {
            float sum = 0.0f;
            #pragma unroll 8
            for (int h2 = 0; h2 < HDIM; h2++)
                sum = fmaf(hsm[sm][h2], w2s[h2 * ODIM + o], sum);
            sum += b2[p * ODIM + o];
            int e = es[sm];
            g_contrib[(size_t)e * ODIM + o] = sum * g_wt[e];
        }
    }
}

// =============== K5: classifier ===============
__global__ void __launch_bounds__(256)
k5_classifier(const float* __restrict__ cw1,
              const float* __restrict__ cb1,
              const float* __restrict__ cw2,
              const float* __restrict__ cb2,
              float* __restrict__ out_logits) {
    int b = threadIdx.x;
    float feat[ODIM];
    #pragma unroll
    for (int o = 0; o < ODIM; o++)
        feat[o] = g_contrib[((size_t)b * TOPK + 0) * ODIM + o]
                + g_contrib[((size_t)b * TOPK + 1) * ODIM + o]
                + g_contrib[((size_t)b * TOPK + 2) * ODIM + o];
    float h8[CHID];
    #pragma unroll
    for (int c = 0; c < CHID; c++) {
        float s = cb1[c];
        #pragma unroll
        for (int o = 0; o < ODIM; o++)
            s = fmaf(feat[o], __ldg(cw1 + o * CHID + c), s);
        h8[c] = fmaxf(s, 0.0f);
    }
    #pragma unroll
    for (int c5 = 0; c5 < NCLS; c5++) {
        float s = cb2[c5];
        #pragma unroll
        for (int c = 0; c < CHID; c++)
            s = fmaf(h8[c], __ldg(cw2 + c * NCLS + c5), s);
        out_logits[(size_t)b * NCLS + c5] = s;
    }
}

// ---------------- launch ----------------
extern "C" void kernel_launch(void* const* d_in, const int* in_sizes, int n_in,
                              void* d_out, int out_size) {
    const float* x_rna    = (const float*)d_in[0];
    const float* x_cnv    = (const float*)d_in[1];
    const float* x_met    = (const float*)d_in[2];
    const float* gene_mask= (const float*)d_in[3];
    const float* gate_w1  = (const float*)d_in[4];
    const float* gate_b1  = (const float*)d_in[5];
    const float* gate_w2  = (const float*)d_in[6];
    const float* gate_b2  = (const float*)d_in[7];
    const float* W1       = (const float*)d_in[8];
    const float* b1       = (const float*)d_in[9];
    const float* bn_gamma = (const float*)d_in[10];
    const float* bn_beta  = (const float*)d_in[11];
    const float* bn_mean  = (const float*)d_in[12];
    const float* bn_var   = (const float*)d_in[13];
    const float* W2       = (const float*)d_in[14];
    const float* b2       = (const float*)d_in[15];
    const float* cls_w1   = (const float*)d_in[16];
    const float* cls_b1   = (const float*)d_in[17];
    const float* cls_w2   = (const float*)d_in[18];
    const float* cls_b2   = (const float*)d_in[19];
    float* out = (float*)d_out;
    float* out_logits = out;
    float* out_gw = out + BATCH * NCLS;

    k1_fused<<<K1_BLOCKS, 256>>>(gene_mask, x_rna, gate_w1);
    k2_gate_finish<<<BATCH, GHID>>>(gate_b1, gate_w2, gate_b2, out_gw);
    k3_sort<<<1, NENT>>>();
    k4_expert<<<MAXTILE * NSEG, 256>>>(x_rna, x_cnv, x_met, W1);
    k4b_finish<<<MAXTILE, 256>>>(b1, bn_gamma, bn_beta, bn_mean, bn_var, W2, b2);
    k5_classifier<<<1, BATCH>>>(cls_w1, cls_b1, cls_w2, cls_b2, out_logits);
}